// round 11
// baseline (speedup 1.0000x reference)
#include <cuda_runtime.h>
#include <cstdint>

// DepthDeformConv: modulated deformable conv 3x3, s=1, p=1, d=1.
// B=4, C=64, H=W=128, O=64, K=9, fp32. Output (4,64,128,128) fp32.
//
// K1 (k_prep): permute weights: g_wt[(cc*72 + cl*9 + k)*64 + o].
// K2 (ddc_main): one block per (b,y); 512 threads; 2 blocks/SM (32 warps/SM).
//   - META (once): 1152 (k,pix) jobs -> short4 plane indices + float4 weights
//   - per chunk cc (8 chunks of 8 channels = 72 col rows):
//       gather: job = (k,pix), NCHW scattered LDG.32 x4 per channel (base
//               addresses reused over 8 channels), value stored DUPLICATED
//               as float2 (v,v) -> col2[row][pix] (STS.64, conflict-free)
//       FMA: warp = 4 outputs x 128 pix, full-K accum in regs (acc = 16 regs).
//            Per row: 2x LDS.128 col (natural (v,v) fma2 operands) +
//            1x uniform LDG.128 weights (natural (w0,w1) pairs) + 8x fma2.
//            ZERO pack/MOV overhead in the hot loop.
//   - epilogue: bias + STG.128 (no reduction).

#define HW 128
#define PLANE 16384
#define CIN 64
#define OOUT 64
#define CKTOT 576
#define NJOBS 1152
#define RPC 72              // rows per chunk (8 ch * 9 k)
#define NCHUNK 8
#define NTHREADS 512

#define OFF_MI 73728                    // col2: [0, 73728) = 72*128*8 bytes
#define OFF_MW (OFF_MI + 9216)          // 82944
#define SMEM_TOTAL (OFF_MW + 18432)     // 101376

typedef unsigned long long ull;

__device__ float g_wt[CKTOT * OOUT];

__device__ __forceinline__ ull pack2(float lo, float hi) {
    ull d;
    asm("mov.b64 %0, {%1, %2};" : "=l"(d) : "f"(lo), "f"(hi));
    return d;
}
__device__ __forceinline__ float2 unpack2(ull v) {
    float2 r;
    asm("mov.b64 {%0, %1}, %2;" : "=f"(r.x), "=f"(r.y) : "l"(v));
    return r;
}
__device__ __forceinline__ ull fma2(ull a, ull b, ull c) {
    ull d;
    asm("fma.rn.f32x2 %0, %1, %2, %3;" : "=l"(d) : "l"(a), "l"(b), "l"(c));
    return d;
}

// ---------------- K1: weight permute ----------------
// g_wt[(cc*72 + cl*9 + k)*64 + o] = w[o*576 + (cc*8+cl)*9 + k]
__global__ __launch_bounds__(256) void k_prep(const float* __restrict__ w) {
    int idx = blockIdx.x * 256 + threadIdx.x;
    if (idx >= OOUT * CKTOT) return;
    int o = idx / CKTOT, rem = idx - o * CKTOT;
    int c = rem / 9, k = rem - c * 9;
    int cc = c >> 3, cl = c & 7;
    g_wt[(cc * RPC + cl * 9 + k) * OOUT + o] = w[idx];
}

// ---------------- K2: main ----------------
extern __shared__ char smraw[];

__global__ __launch_bounds__(NTHREADS, 2)
void ddc_main(const float* __restrict__ input,
              const float* __restrict__ offset,
              const float* __restrict__ mask,
              const float* __restrict__ bias,
              float* __restrict__ out)
{
    char*   colb   = smraw;                      // [72] rows of 128 float2 (1KB/row)
    short4* meta_i = (short4*)(smraw + OFF_MI);
    float4* meta_w = (float4*)(smraw + OFF_MW);

    const int tid = threadIdx.x;
    const int bid = blockIdx.x;
    const int y = bid & 127;
    const int b = bid >> 7;
    const int wid  = tid >> 5;     // 0..15: o-group, o base = wid*4
    const int lane = tid & 31;     // 4-pixel group
    const int og   = wid;

    // ---- META: 1152 jobs, once per block ----
    for (int i = tid; i < NJOBS; i += NTHREADS) {
        int pix = i & 127;
        int k   = i >> 7;
        int ky  = k / 3;
        int kx  = k - ky * 3;

        int ob = ((b * 18 + 2 * k) * HW + y) * HW + pix;
        float oy = __ldg(offset + ob);
        float ox = __ldg(offset + ob + PLANE);
        float m  = __ldg(mask + ((b * 9 + k) * HW + y) * HW + pix);

        float py = (float)(y - 1 + ky) + oy;
        float px = (float)(pix - 1 + kx) + ox;
        float y0f = floorf(py), x0f = floorf(px);
        int y0 = (int)y0f, x0 = (int)x0f;
        float wy = py - y0f, wx = px - x0f;
        int y1 = y0 + 1, x1 = x0 + 1;

        float vy0 = (y0 >= 0 && y0 < HW) ? 1.f : 0.f;
        float vy1 = (y1 >= 0 && y1 < HW) ? 1.f : 0.f;
        float vx0 = (x0 >= 0 && x0 < HW) ? 1.f : 0.f;
        float vx1 = (x1 >= 0 && x1 < HW) ? 1.f : 0.f;
        int yc0 = min(max(y0, 0), HW - 1);
        int yc1 = min(max(y1, 0), HW - 1);
        int xc0 = min(max(x0, 0), HW - 1);
        int xc1 = min(max(x1, 0), HW - 1);

        float4 w;
        w.x = (1.f - wy) * (1.f - wx) * m * vy0 * vx0;
        w.y = (1.f - wy) * wx         * m * vy0 * vx1;
        w.z = wy         * (1.f - wx) * m * vy1 * vx0;
        w.w = wy         * wx         * m * vy1 * vx1;

        meta_i[i] = make_short4((short)(yc0 * HW + xc0), (short)(yc0 * HW + xc1),
                                (short)(yc1 * HW + xc0), (short)(yc1 * HW + xc1));
        meta_w[i] = w;
    }

    // acc[j][q]: o-pair j (o = og*4 + 2j, +2j+1), pixel q (pix = lane*4+q)
    ull acc[2][4];
    #pragma unroll
    for (int j = 0; j < 2; j++)
        #pragma unroll
        for (int q = 0; q < 4; q++) acc[j][q] = 0ULL;

    const float* inb = input + (size_t)b * CIN * PLANE;

    for (int cc = 0; cc < NCHUNK; cc++) {
        __syncthreads();    // meta ready / previous FMA done with col

        // ---- gather: 1152 jobs, 8 channels each; values stored duplicated ----
        const float* pbase = inb + (size_t)(cc * 8) * PLANE;
        for (int i = tid; i < NJOBS; i += NTHREADS) {
            short4 mi = meta_i[i];
            float4 mw = meta_w[i];
            int i00 = (int)mi.x, i01 = (int)mi.y, i10 = (int)mi.z, i11 = (int)mi.w;
            int pix = i & 127;
            int k   = i >> 7;
            char* cdst = colb + (k * 1024) + pix * 8;   // row cl*9+k, pitch 1KB
            #pragma unroll
            for (int cl = 0; cl < 8; cl++) {
                const float* pp = pbase + cl * PLANE;
                float v = mw.x * __ldg(pp + i00) + mw.y * __ldg(pp + i01)
                        + mw.z * __ldg(pp + i10) + mw.w * __ldg(pp + i11);
                *(float2*)(cdst + cl * 9 * 1024) = make_float2(v, v);
            }
        }
        __syncthreads();

        // ---- FMA: 72 rows; per row 3 loads + 8 fma2, zero MOVs ----
        const char* wbase = (const char*)(g_wt + (size_t)cc * RPC * OOUT + og * 4);
        const char* cbase = colb + lane * 32;
        #pragma unroll 4
        for (int row = 0; row < RPC; row++) {
            ulonglong2 ca = *(const ulonglong2*)(cbase + row * 1024);       // (v0,v0),(v1,v1)
            ulonglong2 cb = *(const ulonglong2*)(cbase + row * 1024 + 16);  // (v2,v2),(v3,v3)
            float4 wq = __ldg((const float4*)(wbase + row * 256));          // uniform
            ull wp0 = pack2(wq.x, wq.y);   // free: adjacent regs from LDG.128
            ull wp1 = pack2(wq.z, wq.w);
            acc[0][0] = fma2(wp0, ca.x, acc[0][0]);
            acc[0][1] = fma2(wp0, ca.y, acc[0][1]);
            acc[0][2] = fma2(wp0, cb.x, acc[0][2]);
            acc[0][3] = fma2(wp0, cb.y, acc[0][3]);
            acc[1][0] = fma2(wp1, ca.x, acc[1][0]);
            acc[1][1] = fma2(wp1, ca.y, acc[1][1]);
            acc[1][2] = fma2(wp1, cb.x, acc[1][2]);
            acc[1][3] = fma2(wp1, cb.y, acc[1][3]);
        }
    }

    // ---- epilogue: full-K accs, add bias, store ----
    #pragma unroll
    for (int j = 0; j < 2; j++) {
        int o0 = og * 4 + 2 * j;
        float bv0 = __ldg(bias + o0);
        float bv1 = __ldg(bias + o0 + 1);
        float4 re, ro;
        float2 v;
        v = unpack2(acc[j][0]); re.x = v.x + bv0; ro.x = v.y + bv1;
        v = unpack2(acc[j][1]); re.y = v.x + bv0; ro.y = v.y + bv1;
        v = unpack2(acc[j][2]); re.z = v.x + bv0; ro.z = v.y + bv1;
        v = unpack2(acc[j][3]); re.w = v.x + bv0; ro.w = v.y + bv1;
        size_t base = (size_t)(b * OOUT + o0) * PLANE + y * HW + lane * 4;
        *(float4*)(out + base)         = re;
        *(float4*)(out + base + PLANE) = ro;
    }
}

extern "C" void kernel_launch(void* const* d_in, const int* in_sizes, int n_in,
                              void* d_out, int out_size)
{
    const float* input  = (const float*)d_in[0];
    // d_in[1] = depth, unused by the reference computation
    const float* offset = (const float*)d_in[2];
    const float* mask   = (const float*)d_in[3];
    const float* weight = (const float*)d_in[4];
    const float* bias   = (const float*)d_in[5];
    float* out = (float*)d_out;

    cudaFuncSetAttribute(ddc_main,
                         cudaFuncAttributeMaxDynamicSharedMemorySize, SMEM_TOTAL);

    k_prep<<<(OOUT * CKTOT + 255) / 256, 256>>>(weight);
    ddc_main<<<512, NTHREADS, SMEM_TOTAL>>>(input, offset, mask, bias, out);
}

// round 14
// speedup vs baseline: 2.3317x; 2.3317x over previous
#include <cuda_runtime.h>
#include <cstdint>

// DepthDeformConv: modulated deformable conv 3x3, s=1, p=1, d=1.
// B=4, C=64, H=W=128, O=64, K=9, fp32. Output (4,64,128,128) fp32.
//
// K0 (k_prep): blockIdx.x < 512: repack input NCHW -> NHWC8
//              g_in8[b][g][y*128+x][8]; blockIdx.x >= 512: permute weights
//              g_wt[(cc*72 + k*8 + cl)*64 + o].
// K1 (ddc_main): one block per (b,y); 256 threads; 2 blocks/SM (83KB smem).
//   - META (once): 1152 (k,pix) jobs -> short4 indices + float4 weights
//   - per chunk cc (8 chunks of 8 ch = 72 col rows):
//       stage weights [72][64] -> wsm (18.4KB, coalesced)
//       gather: 4-lane groups, dense 4xLDG.64 NHWC8 taps, swizzled STS
//       FMA: warp = (pix-half, o-half, ck-half); lane = 2 adjacent pixels.
//            Per row: 1 LDS.64 col + 2 packs + 8 LDS.128 broadcast weights
//            + 32 fma2 (fma.rn.f32x2 over o-pairs).
//   - 2-way ck reduction via smem, bias, STG.64 epilogue.

#define HW 128
#define PLANE 16384
#define CIN 64
#define OOUT 64
#define CKTOT 576
#define NJOBS 1152
#define RPC 72
#define NCHUNK 8
#define NTHREADS 256

#define OFF_W  36864                    // col: [0, 36864)
#define OFF_MI (OFF_W + 18432)          // 55296
#define OFF_MW (OFF_MI + 9216)          // 64512
#define SMEM_TOTAL (OFF_MW + 18432)     // 82944

typedef unsigned long long ull;

__device__ float g_in8[4 * 8 * PLANE * 8];   // 16 MB
__device__ float g_wt[CKTOT * OOUT];

__device__ __forceinline__ ull pack2(float lo, float hi) {
    ull d;
    asm("mov.b64 %0, {%1, %2};" : "=l"(d) : "f"(lo), "f"(hi));
    return d;
}
__device__ __forceinline__ float2 unpack2(ull v) {
    float2 r;
    asm("mov.b64 {%0, %1}, %2;" : "=f"(r.x), "=f"(r.y) : "l"(v));
    return r;
}
__device__ __forceinline__ ull fma2(ull a, ull b, ull c) {
    ull d;
    asm("fma.rn.f32x2 %0, %1, %2, %3;" : "=l"(d) : "l"(a), "l"(b), "l"(c));
    return d;
}
__device__ __forceinline__ ull add2(ull a, ull b) {
    ull d;
    asm("add.rn.f32x2 %0, %1, %2;" : "=l"(d) : "l"(a), "l"(b));
    return d;
}

// ---------------- K0: fused prep (input repack + weight permute) ----------------
__global__ __launch_bounds__(256) void k_prep(const float* __restrict__ in,
                                              const float* __restrict__ w) {
    const int bid = blockIdx.x;
    const int tid = threadIdx.x;
    if (bid < 512) {
        // NCHW -> NHWC8 for row (b, y)
        __shared__ float t[64][129];
        const int y = bid & 127, b = bid >> 7;
        const float* ib = in + (size_t)b * CIN * PLANE + y * HW;
        #pragma unroll 8
        for (int it = 0; it < 32; it++) {
            int i = tid + it * 256;
            int c = i >> 7, x = i & 127;
            t[c][x] = __ldg(ib + c * PLANE + x);
        }
        __syncthreads();
        #pragma unroll 8
        for (int it = 0; it < 32; it++) {
            int i = tid + it * 256;
            int cl = i & 7, x = (i >> 3) & 127, g = i >> 10;
            g_in8[(((size_t)(b * 8 + g)) * PLANE + y * HW + x) * 8 + cl] = t[g * 8 + cl][x];
        }
    } else {
        // weight permute: 36864 elements over 144 blocks of 256
        int idx = (bid - 512) * 256 + tid;
        if (idx < OOUT * CKTOT) {
            int o = idx / CKTOT, rem = idx - o * CKTOT;
            int c = rem / 9, k = rem - c * 9;
            int cc = c >> 3, cl = c & 7;
            g_wt[(cc * RPC + k * 8 + cl) * OOUT + o] = w[idx];
        }
    }
}

// ---------------- K1: main ----------------
extern __shared__ char smraw[];

__global__ __launch_bounds__(NTHREADS, 2)
void ddc_main(const float* __restrict__ offset,
              const float* __restrict__ mask,
              const float* __restrict__ bias,
              float* __restrict__ out)
{
    float*  colf   = (float*)smraw;              // [72] rows x 128 f, swizzled
    float*  wsmf   = (float*)(smraw + OFF_W);    // [72] rows x 64 f
    short4* meta_i = (short4*)(smraw + OFF_MI);
    float4* meta_w = (float4*)(smraw + OFF_MW);

    const int tid = threadIdx.x;
    const int bid = blockIdx.x;
    const int y = bid & 127;
    const int b = bid >> 7;
    const int wid  = tid >> 5;
    const int lane = tid & 31;
    const int h    = wid & 1;            // pixel half
    const int g    = (wid >> 1) & 1;     // output half (o base = g*32)
    const int s    = wid >> 2;           // ck half (rows s*36..+36)
    const int pix0 = h * 64 + lane * 2;  // this thread's 2 pixels
    const int grp  = tid >> 2;           // gather group 0..63
    const int p    = tid & 3;            // channel pair within group

    // ---- META: 1152 jobs, once per block ----
    for (int i = tid; i < NJOBS; i += NTHREADS) {
        int pix = i & 127;
        int k   = i >> 7;
        int ky  = k / 3;
        int kx  = k - ky * 3;

        int ob = ((b * 18 + 2 * k) * HW + y) * HW + pix;
        float oy = __ldg(offset + ob);
        float ox = __ldg(offset + ob + PLANE);
        float m  = __ldg(mask + ((b * 9 + k) * HW + y) * HW + pix);

        float py = (float)(y - 1 + ky) + oy;
        float px = (float)(pix - 1 + kx) + ox;
        float y0f = floorf(py), x0f = floorf(px);
        int y0 = (int)y0f, x0 = (int)x0f;
        float wy = py - y0f, wx = px - x0f;
        int y1 = y0 + 1, x1 = x0 + 1;

        float vy0 = (y0 >= 0 && y0 < HW) ? 1.f : 0.f;
        float vy1 = (y1 >= 0 && y1 < HW) ? 1.f : 0.f;
        float vx0 = (x0 >= 0 && x0 < HW) ? 1.f : 0.f;
        float vx1 = (x1 >= 0 && x1 < HW) ? 1.f : 0.f;
        int yc0 = min(max(y0, 0), HW - 1);
        int yc1 = min(max(y1, 0), HW - 1);
        int xc0 = min(max(x0, 0), HW - 1);
        int xc1 = min(max(x1, 0), HW - 1);

        float4 w;
        w.x = (1.f - wy) * (1.f - wx) * m * vy0 * vx0;
        w.y = (1.f - wy) * wx         * m * vy0 * vx1;
        w.z = wy         * (1.f - wx) * m * vy1 * vx0;
        w.w = wy         * wx         * m * vy1 * vx1;

        meta_i[i] = make_short4((short)(yc0 * HW + xc0), (short)(yc0 * HW + xc1),
                                (short)(yc1 * HW + xc0), (short)(yc1 * HW + xc1));
        meta_w[i] = w;
    }

    // acc[j][q]: o-pair j (o = g*32 + 2j, +2j+1), pixel q (pix0+q)
    ull acc[16][2];
    #pragma unroll
    for (int j = 0; j < 16; j++) { acc[j][0] = 0ULL; acc[j][1] = 0ULL; }

    for (int cc = 0; cc < NCHUNK; cc++) {
        __syncthreads();    // meta ready / previous FMA done with col+wsm

        // ---- stage weight chunk [72][64] (coalesced, 1152 float4) ----
        {
            const float4* src = (const float4*)(g_wt + (size_t)cc * RPC * OOUT);
            float4* dst = (float4*)wsmf;
            for (int i = tid; i < 1152; i += NTHREADS)
                dst[i] = src[i];
        }

        // ---- gather: 1152 jobs x 4 lanes, dense NHWC8 taps ----
        const float2* nb = (const float2*)g_in8 + ((size_t)(b * 8 + cc)) * PLANE * 4;
        #pragma unroll 2
        for (int j = grp; j < NJOBS; j += 64) {
            short4 mi = meta_i[j];
            float4 mw = meta_w[j];
            float2 t00 = __ldg(nb + ((int)mi.x << 2) + p);
            float2 t01 = __ldg(nb + ((int)mi.y << 2) + p);
            float2 t10 = __ldg(nb + ((int)mi.z << 2) + p);
            float2 t11 = __ldg(nb + ((int)mi.w << 2) + p);

            float vx_ = mw.x * t00.x + mw.y * t01.x + mw.z * t10.x + mw.w * t11.x;
            float vy_ = mw.x * t00.y + mw.y * t01.y + mw.z * t10.y + mw.w * t11.y;

            int r   = (j >> 7) * 8 + 2 * p;    // k*8 + 2p
            int psw = (j & 127) ^ (p << 3);
            colf[r * 128 + psw]       = vx_;
            colf[(r + 1) * 128 + psw] = vy_;
        }
        __syncthreads();

        // ---- FMA: rows [s*36, s*36+36); 2 pix x 32 outputs per thread ----
        #pragma unroll 4
        for (int row = s * 36; row < s * 36 + 36; row++) {
            int swz = ((row & 7) >> 1) << 3;
            float2 cv = *(const float2*)(colf + row * 128 + (pix0 ^ swz));
            ull cp0 = pack2(cv.x, cv.x);
            ull cp1 = pack2(cv.y, cv.y);
            const float* wrow = wsmf + row * 64 + g * 32;
            #pragma unroll
            for (int i = 0; i < 8; i++) {
                float4 wq = *(const float4*)(wrow + i * 4);   // broadcast LDS.128
                ull wp0 = pack2(wq.x, wq.y);   // free: adjacent regs
                ull wp1 = pack2(wq.z, wq.w);
                acc[2*i][0]   = fma2(wp0, cp0, acc[2*i][0]);
                acc[2*i][1]   = fma2(wp0, cp1, acc[2*i][1]);
                acc[2*i+1][0] = fma2(wp1, cp0, acc[2*i+1][0]);
                acc[2*i+1][1] = fma2(wp1, cp1, acc[2*i+1][1]);
            }
        }
    }

    // ---- reduction across the 2 ck halves (reuse col+wsm area) ----
    ull* pr = (ull*)smraw;   // 128 slots x 32 u64 = 32KB
    const int slot = (wid & 3) * 32 + lane;
    __syncthreads();
    if (s == 1) {
        ull* rowp = pr + slot * 32;
        #pragma unroll
        for (int j = 0; j < 16; j++) {
            rowp[2*j]   = acc[j][0];
            rowp[2*j+1] = acc[j][1];
        }
    }
    __syncthreads();
    if (s == 0) {
        const ull* rowp = pr + slot * 32;
        #pragma unroll
        for (int j = 0; j < 16; j++) {
            int o0 = g * 32 + 2 * j;
            float bv0 = __ldg(bias + o0);
            float bv1 = __ldg(bias + o0 + 1);
            float2 a0 = unpack2(add2(acc[j][0], rowp[2*j]));     // (o0,o0+1)@pix0
            float2 a1 = unpack2(add2(acc[j][1], rowp[2*j+1]));   // (o0,o0+1)@pix0+1
            size_t base = (size_t)(b * OOUT + o0) * PLANE + y * HW + pix0;
            *(float2*)(out + base)         = make_float2(a0.x + bv0, a1.x + bv0);
            *(float2*)(out + base + PLANE) = make_float2(a0.y + bv1, a1.y + bv1);
        }
    }
}

extern "C" void kernel_launch(void* const* d_in, const int* in_sizes, int n_in,
                              void* d_out, int out_size)
{
    const float* input  = (const float*)d_in[0];
    // d_in[1] = depth, unused by the reference computation
    const float* offset = (const float*)d_in[2];
    const float* mask   = (const float*)d_in[3];
    const float* weight = (const float*)d_in[4];
    const float* bias   = (const float*)d_in[5];
    float* out = (float*)d_out;

    cudaFuncSetAttribute(ddc_main,
                         cudaFuncAttributeMaxDynamicSharedMemorySize, SMEM_TOTAL);

    k_prep<<<512 + 144, 256>>>(input, weight);
    ddc_main<<<512, NTHREADS, SMEM_TOTAL>>>(offset, mask, bias, out);
}